// round 6
// baseline (speedup 1.0000x reference)
#include <cuda_runtime.h>
#include <cstdint>

#define A_TOT 68
#define TROWS 64
#define TPB   128
#define F4PT  (TROWS * 17)      // 1088 float4 per tile (17.4 KB)
#define MAXB  2048
#define L2E   1.4426950408889634f
#define LN2   0.6931471805599453f

__device__ float g_partials[MAXB];
__device__ unsigned int g_count = 0;

__constant__ unsigned char c_seg_of[A_TOT] = {
    0,0,0, 1,1,1, 2,2,2,2,
    3,3,3,3,3,3,3,3,3,3,3,3,3,3,3,3,3,3,3,3,3,3,3,3,3,
    4,4,4,4,4,4,4,4,4,4,4,4,4,4,4,4,4,4,4,4,4,4,4,4,4,
    5,5,5,5,5,5,5,5
};
__constant__ int c_seg_beg[6] = {0, 3, 6, 10, 35, 60};
__constant__ int c_seg_end[6] = {3, 6, 10, 35, 60, 68};

// ---------------------------------------------------------------------------
__device__ __forceinline__ void cp16(void* sdst, const void* gsrc) {
    uint32_t s = (uint32_t)__cvta_generic_to_shared(sdst);
    asm volatile("cp.async.cg.shared.global [%0], [%1], 16;\n" :: "r"(s), "l"(gsrc));
}
__device__ __forceinline__ void cp_commit() { asm volatile("cp.async.commit_group;\n"); }
__device__ __forceinline__ void cp_wait1()  { asm volatile("cp.async.wait_group 1;\n"); }

// ---- f32x2 packed helpers (sm_103a FFMA2/FADD2/FMUL2 path) ----------------
__device__ __forceinline__ uint64_t pk(float a, float b) {
    uint64_t r; asm("mov.b64 %0,{%1,%2};" : "=l"(r) : "f"(a), "f"(b)); return r;
}
__device__ __forceinline__ void upk(uint64_t p, float& a, float& b) {
    asm("mov.b64 {%0,%1},%2;" : "=f"(a), "=f"(b) : "l"(p));
}
__device__ __forceinline__ uint64_t mul2(uint64_t a, uint64_t b) {
    uint64_t d; asm("mul.rn.f32x2 %0,%1,%2;" : "=l"(d) : "l"(a), "l"(b)); return d;
}
__device__ __forceinline__ uint64_t fma2(uint64_t a, uint64_t b, uint64_t c) {
    uint64_t d; asm("fma.rn.f32x2 %0,%1,%2,%3;" : "=l"(d) : "l"(a), "l"(b), "l"(c)); return d;
}
__device__ __forceinline__ uint64_t add2(uint64_t a, uint64_t b) {
    uint64_t d; asm("add.rn.f32x2 %0,%1,%2;" : "=l"(d) : "l"(a), "l"(b)); return d;
}
__device__ __forceinline__ float ex2a(float x) {
    float r; asm("ex2.approx.f32 %0,%1;" : "=f"(r) : "f"(x)); return r;
}
__device__ __forceinline__ float lg2a(float x) {
    float r; asm("lg2.approx.f32 %0,%1;" : "=f"(r) : "f"(x)); return r;
}

// Packed accumulators for one segment: S=sum e, W=sum e*u (u=z*log2e), X=sum e*x
struct Acc { uint64_t s, w, x; };
#define ACC0 Acc{0ull, 0ull, 0ull}

__device__ __forceinline__ void step2(Acc& A, uint64_t z2, uint64_t x2, uint64_t l2e2) {
    uint64_t u2 = mul2(z2, l2e2);
    float u0, u1; upk(u2, u0, u1);
    uint64_t e2 = pk(ex2a(u0), ex2a(u1));
    A.s = add2(A.s, e2);
    A.w = fma2(e2, u2, A.w);
    A.x = fma2(e2, x2, A.x);
}
__device__ __forceinline__ void step1(float& s, float& w, float& xs, float z, float x) {
    float u = z * L2E;
    float e = ex2a(u);
    s += e; w = fmaf(e, u, w); xs = fmaf(e, x, xs);
}
// loss_seg = inv_n * ((ln2*W - X)/S - ln2*log2(S))
__device__ __forceinline__ float fin(Acc A, float s1, float w1, float x1, float inv_n) {
    float sa, sb, wa, wb, xa, xb;
    upk(A.s, sa, sb); upk(A.w, wa, wb); upk(A.x, xa, xb);
    float S = sa + sb + s1, Wv = wa + wb + w1, X = xa + xb + x1;
    return inv_n * (__fdividef(fmaf(LN2, Wv, -X), S) - LN2 * lg2a(S));
}

// ---------------------------------------------------------------------------
// Fused persistent kernel: warps 0-1 -> segments 0..3 (elems 0..34),
// warps 2-3 -> segments 4..5 (elems 35..67). 2-stage cp.async double buffer.
// ---------------------------------------------------------------------------
__global__ void __launch_bounds__(TPB, 6)
fused_kernel(const float* __restrict__ cur,
             const float* __restrict__ prev,
             float* __restrict__ out,
             int W, int nblocks, float inv_W) {
    __shared__ float4 buf[2][F4PT];          // 34.8 KB double buffer
    __shared__ float4 sx4[17];               // x as float4 (68 floats)
    __shared__ float  scur[A_TOT];
    __shared__ float  sm6[6], sls6[6];
    __shared__ float  red[TPB / 32];
    __shared__ bool   s_last;

    const int t      = threadIdx.x;
    const int half   = t >> 6;               // 0: segs 0-3, 1: segs 4-5
    const int row    = t & 63;
    const int ntiles = (W + TROWS - 1) / TROWS;
    const int gstep  = (int)gridDim.x;
    const bool wdiv  = (W % TROWS) == 0;
    const uint64_t l2e2 = pk(L2E, L2E);

    // ---- prefetch first tile ----
    int tile = blockIdx.x;
    if (tile < ntiles) {
        const float4* g = (const float4*)prev + (size_t)tile * F4PT + t;
        if (wdiv || tile < ntiles - 1) {
#pragma unroll
            for (int k = 0; k < 8; k++) cp16(&buf[0][t + k * TPB], g + k * TPB);
            if (t < F4PT - 8 * TPB)     cp16(&buf[0][t + 8 * TPB], g + 8 * TPB);
        } else {
            const int n4 = (W - tile * TROWS) * 17;
#pragma unroll
            for (int k = 0; k < 9; k++)
                if (t + k * TPB < n4)   cp16(&buf[0][t + k * TPB], g + k * TPB);
        }
    }
    cp_commit();

    // ---- x = segmented log_softmax(current_action), parallel per block ----
    if (t < A_TOT) scur[t] = cur[t];
    __syncthreads();
    if (t < 6) {
        int b = c_seg_beg[t], e = c_seg_end[t];
        float m = -1e30f;
        for (int i = b; i < e; i++) m = fmaxf(m, scur[i]);
        float sum = 0.f;
        for (int i = b; i < e; i++) sum += ex2a((scur[i] - m) * L2E);
        sm6[t]  = m;
        sls6[t] = LN2 * lg2a(sum);
    }
    __syncthreads();
    if (t < A_TOT) {
        int sg = c_seg_of[t];
        ((float*)sx4)[t] = scur[t] - sm6[sg] - sls6[sg];
    }
    // (sx visibility covered by the pipeline __syncthreads below)

    // ---- main pipelined loop ----
    float acc = 0.f;
    int stage = 0;
    for (; tile < ntiles; tile += gstep) {
        const int nxt = tile + gstep;
        if (nxt < ntiles) {
            const float4* g = (const float4*)prev + (size_t)nxt * F4PT + t;
            float4* b = buf[stage ^ 1];
            if (wdiv || nxt < ntiles - 1) {
#pragma unroll
                for (int k = 0; k < 8; k++) cp16(&b[t + k * TPB], g + k * TPB);
                if (t < F4PT - 8 * TPB)     cp16(&b[t + 8 * TPB], g + 8 * TPB);
            } else {
                const int n4 = (W - nxt * TROWS) * 17;
#pragma unroll
                for (int k = 0; k < 9; k++)
                    if (t + k * TPB < n4)   cp16(&b[t + k * TPB], g + k * TPB);
            }
        }
        cp_commit();
        cp_wait1();          // current tile's group complete
        __syncthreads();

        const int rows_here = (wdiv || tile < ntiles - 1) ? TROWS : (W - tile * TROWS);
        if (row < rows_here) {
            const int off = half ? 8 : 0;
            const float4* rp = &buf[stage][row * 17 + off];  // conflict-free LDS.128
            const float4* sp = &sx4[off];                    // broadcast LDS.128
            float4 z, q;
            if (half == 0) {
                Acc A0 = ACC0, A1 = ACC0, A2 = ACC0, A3 = ACC0;
                float s0 = 0, w0 = 0, x0 = 0;   // seg0 scalar (elem 2)
                float s1 = 0, w1 = 0, x1 = 0;   // seg1 scalar (elem 3)
                float s3 = 0, w3 = 0, x3 = 0;   // seg3 scalar (elem 34)
                z = rp[0]; q = sp[0];
                step2(A0, pk(z.x, z.y), pk(q.x, q.y), l2e2);   // 0,1
                step1(s0, w0, x0, z.z, q.z);                   // 2
                step1(s1, w1, x1, z.w, q.w);                   // 3
                z = rp[1]; q = sp[1];
                step2(A1, pk(z.x, z.y), pk(q.x, q.y), l2e2);   // 4,5
                step2(A2, pk(z.z, z.w), pk(q.z, q.w), l2e2);   // 6,7
                z = rp[2]; q = sp[2];
                step2(A2, pk(z.x, z.y), pk(q.x, q.y), l2e2);   // 8,9
                step2(A3, pk(z.z, z.w), pk(q.z, q.w), l2e2);   // 10,11
#pragma unroll
                for (int j = 3; j < 8; j++) {                  // 12..31
                    z = rp[j]; q = sp[j];
                    step2(A3, pk(z.x, z.y), pk(q.x, q.y), l2e2);
                    step2(A3, pk(z.z, z.w), pk(q.z, q.w), l2e2);
                }
                z = rp[8]; q = sp[8];
                step2(A3, pk(z.x, z.y), pk(q.x, q.y), l2e2);   // 32,33
                step1(s3, w3, x3, z.z, q.z);                   // 34
                acc += fin(A0, s0, w0, x0, 1.f / 3.f);
                acc += fin(A1, s1, w1, x1, 1.f / 3.f);
                acc += fin(A2, 0.f, 0.f, 0.f, 0.25f);
                acc += fin(A3, s3, w3, x3, 0.04f);
            } else {
                Acc A4 = ACC0, A5 = ACC0;
                float s4 = 0, w4 = 0, x4 = 0;   // seg4 scalar (elem 35)
                z = rp[0]; q = sp[0];
                step1(s4, w4, x4, z.w, q.w);                   // 35
#pragma unroll
                for (int j = 1; j < 7; j++) {                  // 36..59
                    z = rp[j]; q = sp[j];
                    step2(A4, pk(z.x, z.y), pk(q.x, q.y), l2e2);
                    step2(A4, pk(z.z, z.w), pk(q.z, q.w), l2e2);
                }
#pragma unroll
                for (int j = 7; j < 9; j++) {                  // 60..67
                    z = rp[j]; q = sp[j];
                    step2(A5, pk(z.x, z.y), pk(q.x, q.y), l2e2);
                    step2(A5, pk(z.z, z.w), pk(q.z, q.w), l2e2);
                }
                acc += fin(A4, s4, w4, x4, 0.04f);
                acc += fin(A5, 0.f, 0.f, 0.f, 0.125f);
            }
        }
        __syncthreads();     // buffer reuse guard
        stage ^= 1;
    }

    // ---- deterministic block reduction (4 warps) ----
#pragma unroll
    for (int o = 16; o > 0; o >>= 1)
        acc += __shfl_xor_sync(0xffffffffu, acc, o);
    if ((t & 31) == 0) red[t >> 5] = acc;
    __syncthreads();

    if (t == 0) {
        g_partials[blockIdx.x] = red[0] + red[1] + red[2] + red[3];
        __threadfence();
        unsigned int done = atomicAdd(&g_count, 1u);
        s_last = (done == (unsigned)nblocks - 1u);
    }
    __syncthreads();

    // ---- last block: deterministic final reduction (fixed strided order) ----
    if (s_last) {
        float a = 0.f;
        for (int i = t; i < nblocks; i += TPB)
            a += g_partials[i];
#pragma unroll
        for (int o = 16; o > 0; o >>= 1)
            a += __shfl_xor_sync(0xffffffffu, a, o);
        if ((t & 31) == 0) red[t >> 5] = a;
        __syncthreads();
        if (t == 0) {
            out[0] = (red[0] + red[1] + red[2] + red[3]) * inv_W;
            g_count = 0;     // reset for next graph replay
        }
    }
}

// ---------------------------------------------------------------------------
extern "C" void kernel_launch(void* const* d_in, const int* in_sizes, int n_in,
                              void* d_out, int out_size) {
    const float* cur  = (const float*)d_in[0];
    const float* prev = (const float*)d_in[1];
    float* out = (float*)d_out;

    int W = in_sizes[1] / A_TOT;
    int ntiles = (W + TROWS - 1) / TROWS;          // 8192 for W=524288
    int nblocks = 148 * 6;                          // 6 blocks/SM (smem-limited)
    if (nblocks > ntiles) nblocks = ntiles;
    if (nblocks > MAXB)   nblocks = MAXB;

    fused_kernel<<<nblocks, TPB>>>(cur, prev, out, W, nblocks, 1.0f / (float)W);
}